// round 3
// baseline (speedup 1.0000x reference)
#include <cuda_runtime.h>

#define NN 50000
#define NE 600000
#define HID 128
#define NG 64

// ---- device scratch (no allocations allowed) ----
__device__ int   g_cnt[3][NN];
__device__ float g_dinv[3][NN];
__device__ int   g_off[NN + 1];
__device__ int   g_cur[NN];
__device__ unsigned g_csr[NE];
__device__ __align__(16) float g_h[3][NN * HID];  // 0: gemm out, 1/2: activations
__device__ __align__(16) float g_pool[NG * HID];
__device__ float g_pcnt[NG];

// ---------------- init ----------------
__global__ void k_zero() {
    int i = blockIdx.x * blockDim.x + threadIdx.x;
    if (i < NN) { g_cnt[0][i] = 0; g_cnt[1][i] = 0; g_cnt[2][i] = 0; }
    if (i < NG * HID) g_pool[i] = 0.0f;
    if (i < NG) g_pcnt[i] = 0.0f;
}

// ---------------- degree histogram (int32 inputs!) ----------------
__global__ void k_hist(const int* __restrict__ ei,
                       const int* __restrict__ em) {
    int e = blockIdx.x * blockDim.x + threadIdx.x;
    if (e >= NE) return;
    int d = ei[NE + e];
    int m = em[e];
    atomicAdd(&g_cnt[0][d], 1);
    if (m == 1) atomicAdd(&g_cnt[1][d], 1);
    else if (m == 2) atomicAdd(&g_cnt[2][d], 1);
}

// ---------------- deg^-1/2 ----------------
__global__ void k_dinv() {
    int i = blockIdx.x * blockDim.x + threadIdx.x;
    if (i >= NN) return;
    g_dinv[0][i] = rsqrtf((float)(g_cnt[0][i] + 1));
    g_dinv[1][i] = rsqrtf((float)(g_cnt[1][i] + 1));
    g_dinv[2][i] = rsqrtf((float)(g_cnt[2][i] + 1));
}

// ---------------- single-block exclusive scan over g_cnt[0] ----------------
#define SCAN_T 1024
#define SCAN_CH 49   // 1024*49 = 50176 >= 50000
__global__ void k_scan() {
    __shared__ int ssum[SCAN_T];
    int t = threadIdx.x;
    int base = t * SCAN_CH;
    int s = 0;
    for (int j = 0; j < SCAN_CH; j++) {
        int idx = base + j;
        if (idx < NN) s += g_cnt[0][idx];
    }
    int mysum = s;
    ssum[t] = s;
    __syncthreads();
    for (int d = 1; d < SCAN_T; d <<= 1) {
        int v = (t >= d) ? ssum[t - d] : 0;
        __syncthreads();
        ssum[t] += v;
        __syncthreads();
    }
    int prefix = ssum[t] - mysum;   // exclusive
    for (int j = 0; j < SCAN_CH; j++) {
        int idx = base + j;
        if (idx < NN) {
            g_off[idx] = prefix;
            g_cur[idx] = prefix;
            prefix += g_cnt[0][idx];
        }
    }
    if (t == SCAN_T - 1) g_off[NN] = ssum[SCAN_T - 1];
}

// ---------------- CSR scatter (src in low 16 bits, mask in [16:18)) ----------------
__global__ void k_scatter(const int* __restrict__ ei,
                          const int* __restrict__ em) {
    int e = blockIdx.x * blockDim.x + threadIdx.x;
    if (e >= NE) return;
    int s = ei[e];
    int d = ei[NE + e];
    int m = em[e];
    int pos = atomicAdd(&g_cur[d], 1);
    g_csr[pos] = (unsigned)s | ((unsigned)m << 16);   // s < 50000 < 2^16
}

// ---------------- GEMM: g_h[0] = IN @ W  (N x 128 @ 128 x 128) ----------------
// 256 threads, 8 warps; warp w computes rows [blk*64 + w*8, +8) x 128 cols.
// K tiled by 32: Ws 32x128 (16KB) + Xs 64x33 (8.25KB) static smem.
__global__ void k_gemm(int inSel,              // -1: external X, else g_h[inSel]
                       const float* __restrict__ Xext,
                       const float* __restrict__ W) {
    __shared__ float Ws[32][HID];
    __shared__ float Xs[64][33];
    const float* X = (inSel < 0) ? Xext : g_h[inSel];

    int tid  = threadIdx.x;
    int lane = tid & 31;
    int w    = tid >> 5;
    int rowBase = blockIdx.x * 64;

    float4 acc[8];
#pragma unroll
    for (int r = 0; r < 8; r++) acc[r] = make_float4(0.f, 0.f, 0.f, 0.f);

    for (int kt = 0; kt < HID; kt += 32) {
#pragma unroll
        for (int i = 0; i < 4; i++) {
            int idx = (tid + i * 256) * 4;        // flat float index into 32x128
            int kr = idx >> 7, kc = idx & 127;
            *(float4*)&Ws[kr][kc] = *(const float4*)&W[(kt + kr) * HID + kc];
        }
        for (int i = tid; i < 64 * 8; i += 256) { // 8 float4 per row
            int r = i >> 3, c = (i & 7) * 4;
            int row = rowBase + r;
            float4 v = make_float4(0.f, 0.f, 0.f, 0.f);
            if (row < NN) v = *(const float4*)&X[(size_t)row * HID + kt + c];
            Xs[r][c] = v.x; Xs[r][c + 1] = v.y; Xs[r][c + 2] = v.z; Xs[r][c + 3] = v.w;
        }
        __syncthreads();

#pragma unroll 8
        for (int k = 0; k < 32; k++) {
            float4 wv = *(float4*)&Ws[k][lane * 4];
#pragma unroll
            for (int r = 0; r < 8; r++) {
                float a = Xs[w * 8 + r][k];
                acc[r].x += a * wv.x;
                acc[r].y += a * wv.y;
                acc[r].z += a * wv.z;
                acc[r].w += a * wv.w;
            }
        }
        __syncthreads();
    }

#pragma unroll
    for (int r = 0; r < 8; r++) {
        int row = rowBase + w * 8 + r;
        if (row < NN)
            *(float4*)&g_h[0][(size_t)row * HID + lane * 4] = acc[r];
    }
}

// ---------------- aggregation: warp per node ----------------
// reads g_h[0], writes g_h[outSel]; mode: 0 all, 1 mask==1, 2 mask==2
__global__ void k_agg(int layer, int outSel,
                      const float* __restrict__ bias,
                      int mode, int do_relu) {
    int wi = (blockIdx.x * blockDim.x + threadIdx.x) >> 5;
    if (wi >= NN) return;
    int lane = threadIdx.x & 31;

    const float* dinv = g_dinv[layer];
    float di = dinv[wi];
    int e0 = g_off[wi], e1 = g_off[wi + 1];

    float ax = 0.f, ay = 0.f, az = 0.f, aw = 0.f;
    for (int e = e0; e < e1; e++) {
        unsigned p = g_csr[e];
        int m = (int)(p >> 16);
        if (mode == 0 || m == mode) {
            int s = (int)(p & 0xFFFFu);
            float c = di * dinv[s];
            float4 hv = *(const float4*)&g_h[0][(size_t)s * HID + lane * 4];
            ax += c * hv.x; ay += c * hv.y; az += c * hv.z; aw += c * hv.w;
        }
    }
    float4 hs = *(const float4*)&g_h[0][(size_t)wi * HID + lane * 4];
    float c2 = di * di;
    ax += c2 * hs.x; ay += c2 * hs.y; az += c2 * hs.z; aw += c2 * hs.w;

    float4 bv = *(const float4*)&bias[lane * 4];
    ax += bv.x; ay += bv.y; az += bv.z; aw += bv.w;

    if (do_relu) {
        ax = fmaxf(ax, 0.f); ay = fmaxf(ay, 0.f);
        az = fmaxf(az, 0.f); aw = fmaxf(aw, 0.f);
    }
    float4 o; o.x = ax; o.y = ay; o.z = az; o.w = aw;
    *(float4*)&g_h[outSel][(size_t)wi * HID + lane * 4] = o;
}

// ---------------- global mean pool (sums) over g_h[sel] ----------------
__global__ void k_pool(const int* __restrict__ batch, int sel) {
    int wi = (blockIdx.x * blockDim.x + threadIdx.x) >> 5;
    if (wi >= NN) return;
    int lane = threadIdx.x & 31;
    int g = batch[wi];
    float4 hv = *(const float4*)&g_h[sel][(size_t)wi * HID + lane * 4];
    float* base = &g_pool[g * HID + lane * 4];
    atomicAdd(base + 0, hv.x);
    atomicAdd(base + 1, hv.y);
    atomicAdd(base + 2, hv.z);
    atomicAdd(base + 3, hv.w);
    if (lane == 0) atomicAdd(&g_pcnt[g], 1.0f);
}

// ---------------- head ----------------
__global__ void k_final(const float* __restrict__ Wl,
                        const float* __restrict__ bl,
                        float* __restrict__ out) {
    int g = blockIdx.x;
    int lane = threadIdx.x;
    float inv = 1.0f / fmaxf(g_pcnt[g], 1.0f);
    float s = 0.f;
    for (int j = lane; j < HID; j += 32)
        s += g_pool[g * HID + j] * inv * Wl[j];
#pragma unroll
    for (int o = 16; o; o >>= 1) s += __shfl_xor_sync(0xFFFFFFFFu, s, o);
    if (lane == 0) out[g] = s + bl[0];
}

// ---------------- launcher: kernel launches ONLY ----------------
extern "C" void kernel_launch(void* const* d_in, const int* in_sizes, int n_in,
                              void* d_out, int out_size) {
    const float* x     = (const float*)d_in[0];
    const int*   ei    = (const int*)d_in[1];    // int32 (JAX x64 disabled)
    const int*   em    = (const int*)d_in[2];
    const int*   batch = (const int*)d_in[3];
    const float* W1 = (const float*)d_in[4];
    const float* b1 = (const float*)d_in[5];
    const float* W2 = (const float*)d_in[6];
    const float* b2 = (const float*)d_in[7];
    const float* W3 = (const float*)d_in[8];
    const float* b3 = (const float*)d_in[9];
    const float* Wl = (const float*)d_in[10];
    const float* bl = (const float*)d_in[11];
    float* out = (float*)d_out;

    const int tb  = 256;
    const int gbN = (NN + tb - 1) / tb;
    const int gbE = (NE + tb - 1) / tb;
    const int gbW = (NN * 32 + tb - 1) / tb;   // warp-per-node
    const int gbG = (NN + 63) / 64;            // gemm: 64 rows/block

    k_zero   <<<gbN, tb>>>();
    k_hist   <<<gbE, tb>>>(ei, em);
    k_dinv   <<<gbN, tb>>>();
    k_scan   <<<1, SCAN_T>>>();
    k_scatter<<<gbE, tb>>>(ei, em);

    // layer 1: x -> g_h[0] -> g_h[1] (relu, all edges)
    k_gemm<<<gbG, tb>>>(-1, x, W1);
    k_agg <<<gbW, tb>>>(0, 1, b1, 0, 1);
    // layer 2: g_h[1] -> g_h[0] -> g_h[2] (relu, mask==1)
    k_gemm<<<gbG, tb>>>(1, x, W2);
    k_agg <<<gbW, tb>>>(1, 2, b2, 1, 1);
    // layer 3: g_h[2] -> g_h[0] -> g_h[1] (no relu, mask==2)
    k_gemm<<<gbG, tb>>>(2, x, W3);
    k_agg <<<gbW, tb>>>(2, 1, b3, 2, 0);

    k_pool <<<gbW, tb>>>(batch, 1);
    k_final<<<NG, 32>>>(Wl, bl, out);
}

// round 4
// speedup vs baseline: 1.2131x; 1.2131x over previous
#include <cuda_runtime.h>

#define NN 50000
#define NE 600000
#define HID 128
#define NG 64
#define NBLK 196   // ceil(50000/256)

// ---- device scratch (no allocations allowed) ----
__device__ int   g_cnt[3][NN];
__device__ float g_dinv[3][NN];
__device__ int   g_off[NN + 1];
__device__ int   g_cur[NN];
__device__ int   g_bsum[NBLK];
__device__ int   g_bpre[NBLK];
__device__ unsigned g_csr[NE];
__device__ __align__(16) float g_h[3][NN * HID];  // 0: gemm out, 1/2: activations
__device__ __align__(16) float g_pool[NG * HID];
__device__ float g_pcnt[NG];

// ---------------- init ----------------
__global__ void k_zero() {
    int i = blockIdx.x * blockDim.x + threadIdx.x;
    if (i < NN) { g_cnt[0][i] = 0; g_cnt[1][i] = 0; g_cnt[2][i] = 0; }
    if (i < NG * HID) g_pool[i] = 0.0f;
    if (i < NG) g_pcnt[i] = 0.0f;
}

// ---------------- degree histogram ----------------
__global__ void k_hist(const int* __restrict__ ei,
                       const int* __restrict__ em) {
    int e = blockIdx.x * blockDim.x + threadIdx.x;
    if (e >= NE) return;
    int d = ei[NE + e];
    int m = em[e];
    atomicAdd(&g_cnt[0][d], 1);
    if (m == 1) atomicAdd(&g_cnt[1][d], 1);
    else if (m == 2) atomicAdd(&g_cnt[2][d], 1);
}

// ---------------- deg^-1/2 ----------------
__global__ void k_dinv() {
    int i = blockIdx.x * blockDim.x + threadIdx.x;
    if (i >= NN) return;
    g_dinv[0][i] = rsqrtf((float)(g_cnt[0][i] + 1));
    g_dinv[1][i] = rsqrtf((float)(g_cnt[1][i] + 1));
    g_dinv[2][i] = rsqrtf((float)(g_cnt[2][i] + 1));
}

// ---------------- scan pass A: per-block sums ----------------
__global__ void k_scanA() {
    int i = blockIdx.x * 256 + threadIdx.x;
    int lane = threadIdx.x & 31, warp = threadIdx.x >> 5;
    int v = (i < NN) ? g_cnt[0][i] : 0;
#pragma unroll
    for (int o = 16; o; o >>= 1) v += __shfl_xor_sync(0xFFFFFFFFu, v, o);
    __shared__ int ws[8];
    if (lane == 0) ws[warp] = v;
    __syncthreads();
    if (threadIdx.x == 0) {
        int s = 0;
#pragma unroll
        for (int j = 0; j < 8; j++) s += ws[j];
        g_bsum[blockIdx.x] = s;
    }
}

// ---------------- scan pass B: scan 196 block sums (1 block) ----------------
__global__ void k_scanB() {
    __shared__ int sh[256];
    int t = threadIdx.x;
    int v = (t < NBLK) ? g_bsum[t] : 0;
    sh[t] = v;
    __syncthreads();
    for (int d = 1; d < 256; d <<= 1) {
        int u = (t >= d) ? sh[t - d] : 0;
        __syncthreads();
        sh[t] += u;
        __syncthreads();
    }
    if (t < NBLK) g_bpre[t] = sh[t] - v;          // exclusive
    if (t == NBLK - 1) g_off[NN] = sh[t];         // total
}

// ---------------- scan pass C: local scan + apply prefix ----------------
__global__ void k_scanC() {
    int i = blockIdx.x * 256 + threadIdx.x;
    int lane = threadIdx.x & 31, warp = threadIdx.x >> 5;
    int v = (i < NN) ? g_cnt[0][i] : 0;
    int incl = v;
#pragma unroll
    for (int o = 1; o < 32; o <<= 1) {
        int t = __shfl_up_sync(0xFFFFFFFFu, incl, o);
        if (lane >= o) incl += t;
    }
    __shared__ int ws[8];
    if (lane == 31) ws[warp] = incl;
    __syncthreads();
    if (warp == 0 && lane < 8) {
        int s = ws[lane];
        int si = s;
#pragma unroll
        for (int o = 1; o < 8; o <<= 1) {
            int t = __shfl_up_sync(0xFFu, si, o);
            if (lane >= o) si += t;
        }
        ws[lane] = si - s;   // exclusive warp prefix
    }
    __syncthreads();
    if (i < NN) {
        int excl = (incl - v) + ws[warp] + g_bpre[blockIdx.x];
        g_off[i] = excl;
        g_cur[i] = excl;
    }
}

// ---------------- CSR scatter ----------------
__global__ void k_scatter(const int* __restrict__ ei,
                          const int* __restrict__ em) {
    int e = blockIdx.x * blockDim.x + threadIdx.x;
    if (e >= NE) return;
    int s = ei[e];
    int d = ei[NE + e];
    int m = em[e];
    int pos = atomicAdd(&g_cur[d], 1);
    g_csr[pos] = (unsigned)s | ((unsigned)m << 16);   // s < 50000 < 2^16
}

// ---------------- packed f32x2 FMA helpers ----------------
union F2 { float2 f; unsigned long long u; };
union WV { float4 f4; unsigned long long u[2]; };

#define FFMA2(d, a, b) \
    asm("fma.rn.f32x2 %0, %1, %2, %0;" : "+l"((d).u) : "l"((a).u), "l"((b).u))
#define PACK2(d, s) \
    asm("mov.b64 %0, {%1, %1};" : "=l"((d).u) : "f"(s))

// ---------------- GEMM: g_h[0] = IN @ W  (N x 128 @ 128 x 128) ----------------
// 256 threads, 8 warps; warp w computes rows [blk*64 + w*8, +8) x 128 cols.
// Inner product via fma.rn.f32x2 (2 FMA / issue slot).
__global__ void k_gemm(int inSel,              // -1: external X, else g_h[inSel]
                       const float* __restrict__ Xext,
                       const float* __restrict__ W) {
    __shared__ float Ws[32][HID];
    __shared__ float Xs[64][33];
    const float* X = (inSel < 0) ? Xext : g_h[inSel];

    int tid  = threadIdx.x;
    int lane = tid & 31;
    int w    = tid >> 5;
    int rowBase = blockIdx.x * 64;

    F2 acc[8][2];
#pragma unroll
    for (int r = 0; r < 8; r++) {
        acc[r][0].f = make_float2(0.f, 0.f);
        acc[r][1].f = make_float2(0.f, 0.f);
    }

    for (int kt = 0; kt < HID; kt += 32) {
#pragma unroll
        for (int i = 0; i < 4; i++) {
            int idx = (tid + i * 256) * 4;        // flat float index into 32x128
            int kr = idx >> 7, kc = idx & 127;
            *(float4*)&Ws[kr][kc] = *(const float4*)&W[(kt + kr) * HID + kc];
        }
        for (int i = tid; i < 64 * 8; i += 256) { // 8 float4 per row
            int r = i >> 3, c = (i & 7) * 4;
            int row = rowBase + r;
            float4 v = make_float4(0.f, 0.f, 0.f, 0.f);
            if (row < NN) v = *(const float4*)&X[(size_t)row * HID + kt + c];
            Xs[r][c] = v.x; Xs[r][c + 1] = v.y; Xs[r][c + 2] = v.z; Xs[r][c + 3] = v.w;
        }
        __syncthreads();

#pragma unroll 4
        for (int k = 0; k < 32; k++) {
            WV wv;
            wv.f4 = *(float4*)&Ws[k][lane * 4];
            F2 w01, w23;
            w01.u = wv.u[0];
            w23.u = wv.u[1];
#pragma unroll
            for (int r = 0; r < 8; r++) {
                float a = Xs[w * 8 + r][k];
                F2 ap;
                PACK2(ap, a);
                FFMA2(acc[r][0], ap, w01);
                FFMA2(acc[r][1], ap, w23);
            }
        }
        __syncthreads();
    }

#pragma unroll
    for (int r = 0; r < 8; r++) {
        int row = rowBase + w * 8 + r;
        if (row < NN) {
            float4 o;
            o.x = acc[r][0].f.x; o.y = acc[r][0].f.y;
            o.z = acc[r][1].f.x; o.w = acc[r][1].f.y;
            *(float4*)&g_h[0][(size_t)row * HID + lane * 4] = o;
        }
    }
}

// ---------------- aggregation: warp per node ----------------
// reads g_h[0], writes g_h[outSel]; mode: 0 all, 1 mask==1, 2 mask==2
// doPool: also accumulate mean-pool sums (layer 3)
__global__ void k_agg(int layer, int outSel,
                      const float* __restrict__ bias,
                      int mode, int do_relu,
                      int doPool, const int* __restrict__ batch) {
    int wi = (blockIdx.x * blockDim.x + threadIdx.x) >> 5;
    if (wi >= NN) return;
    int lane = threadIdx.x & 31;

    const float* dinv = g_dinv[layer];
    float di = dinv[wi];
    int e0 = g_off[wi], e1 = g_off[wi + 1];

    float ax = 0.f, ay = 0.f, az = 0.f, aw = 0.f;
    for (int e = e0; e < e1; e++) {
        unsigned p = g_csr[e];
        int m = (int)(p >> 16);
        if (mode == 0 || m == mode) {
            int s = (int)(p & 0xFFFFu);
            float c = di * dinv[s];
            float4 hv = *(const float4*)&g_h[0][(size_t)s * HID + lane * 4];
            ax += c * hv.x; ay += c * hv.y; az += c * hv.z; aw += c * hv.w;
        }
    }
    float4 hs = *(const float4*)&g_h[0][(size_t)wi * HID + lane * 4];
    float c2 = di * di;
    ax += c2 * hs.x; ay += c2 * hs.y; az += c2 * hs.z; aw += c2 * hs.w;

    float4 bv = *(const float4*)&bias[lane * 4];
    ax += bv.x; ay += bv.y; az += bv.z; aw += bv.w;

    if (do_relu) {
        ax = fmaxf(ax, 0.f); ay = fmaxf(ay, 0.f);
        az = fmaxf(az, 0.f); aw = fmaxf(aw, 0.f);
    }
    float4 o; o.x = ax; o.y = ay; o.z = az; o.w = aw;
    *(float4*)&g_h[outSel][(size_t)wi * HID + lane * 4] = o;

    if (doPool) {
        int g = batch[wi];
        float* base = &g_pool[g * HID + lane * 4];
        atomicAdd(base + 0, ax);
        atomicAdd(base + 1, ay);
        atomicAdd(base + 2, az);
        atomicAdd(base + 3, aw);
        if (lane == 0) atomicAdd(&g_pcnt[g], 1.0f);
    }
}

// ---------------- head ----------------
__global__ void k_final(const float* __restrict__ Wl,
                        const float* __restrict__ bl,
                        float* __restrict__ out) {
    int g = blockIdx.x;
    int lane = threadIdx.x;
    float inv = 1.0f / fmaxf(g_pcnt[g], 1.0f);
    float s = 0.f;
    for (int j = lane; j < HID; j += 32)
        s += g_pool[g * HID + j] * inv * Wl[j];
#pragma unroll
    for (int o = 16; o; o >>= 1) s += __shfl_xor_sync(0xFFFFFFFFu, s, o);
    if (lane == 0) out[g] = s + bl[0];
}

// ---------------- launcher: kernel launches ONLY ----------------
extern "C" void kernel_launch(void* const* d_in, const int* in_sizes, int n_in,
                              void* d_out, int out_size) {
    const float* x     = (const float*)d_in[0];
    const int*   ei    = (const int*)d_in[1];    // int32 (JAX x64 disabled)
    const int*   em    = (const int*)d_in[2];
    const int*   batch = (const int*)d_in[3];
    const float* W1 = (const float*)d_in[4];
    const float* b1 = (const float*)d_in[5];
    const float* W2 = (const float*)d_in[6];
    const float* b2 = (const float*)d_in[7];
    const float* W3 = (const float*)d_in[8];
    const float* b3 = (const float*)d_in[9];
    const float* Wl = (const float*)d_in[10];
    const float* bl = (const float*)d_in[11];
    float* out = (float*)d_out;

    const int tb  = 256;
    const int gbN = (NN + tb - 1) / tb;
    const int gbE = (NE + tb - 1) / tb;
    const int gbW = (NN * 32 + tb - 1) / tb;   // warp-per-node
    const int gbG = (NN + 63) / 64;            // gemm: 64 rows/block

    k_zero   <<<gbN, tb>>>();
    k_hist   <<<gbE, tb>>>(ei, em);
    k_dinv   <<<gbN, tb>>>();
    k_scanA  <<<NBLK, 256>>>();
    k_scanB  <<<1, 256>>>();
    k_scanC  <<<NBLK, 256>>>();
    k_scatter<<<gbE, tb>>>(ei, em);

    // layer 1: x -> g_h[0] -> g_h[1] (relu, all edges)
    k_gemm<<<gbG, tb>>>(-1, x, W1);
    k_agg <<<gbW, tb>>>(0, 1, b1, 0, 1, 0, batch);
    // layer 2: g_h[1] -> g_h[0] -> g_h[2] (relu, mask==1)
    k_gemm<<<gbG, tb>>>(1, x, W2);
    k_agg <<<gbW, tb>>>(1, 2, b2, 1, 1, 0, batch);
    // layer 3: g_h[2] -> g_h[0] -> g_h[1] (no relu, mask==2) + fused pool
    k_gemm<<<gbG, tb>>>(2, x, W3);
    k_agg <<<gbW, tb>>>(2, 1, b3, 2, 0, 1, batch);

    k_final<<<NG, 32>>>(Wl, bl, out);
}